// round 4
// baseline (speedup 1.0000x reference)
#include <cuda_runtime.h>
#include <cstdint>

// ============================================================================
// TensorDense via explicit-W:  out = relu(x @ W + bias)
//   W[(i,j,k),(a,b,c)] = sum_q (sum_p c1[i,a,p] c2[j,b,p,q]) c3[k,c,q]
// GEMM on int8 tensor cores (mma.sync.m16n8k32.s8, s32 accum), fixed-point
// split:  x ~= sx*(256*xh+xl),  W ~= sw*(256*wh+wl)
//   out  = sx*sw*( 65536*S(xh,wh) + 256*(S(xh,wl)+S(xl,wh)) )   [xl*wl dropped]
// Scales from runtime |max| reductions (deterministic, graph-safe).
// ============================================================================

#define MODE 16
#define KDIM 4096
#define NDIM 4096
#define BATCH 2048

// scratch (device globals; no allocation)
__device__ float  g_W12[256 * 256 * 32];               // [ia][jb][q]  8MB
__device__ float  g_Wf[(size_t)NDIM * KDIM];           // fp32 W^T [n][k] 64MB
__device__ int8_t g_xh[(size_t)BATCH * KDIM];
__device__ int8_t g_xl[(size_t)BATCH * KDIM];
__device__ int8_t g_wh[(size_t)NDIM * KDIM];           // [n][k]
__device__ int8_t g_wl[(size_t)NDIM * KDIM];
__device__ int    g_xmax_i, g_wmax_i;                  // |max| as float bits
__device__ float  g_sx, g_sw;

// ---------------------------------------------------------------------------
// helpers
// ---------------------------------------------------------------------------
__device__ __forceinline__ uint32_t smem_u32(const void* p) {
    uint32_t a;
    asm("{ .reg .u64 t; cvta.to.shared.u64 t, %1; cvt.u32.u64 %0, t; }"
        : "=r"(a) : "l"(p));
    return a;
}
__device__ __forceinline__ void cp_async16(uint32_t s, const void* g) {
    asm volatile("cp.async.cg.shared.global [%0], [%1], 16;" :: "r"(s), "l"(g));
}
#define CP_COMMIT() asm volatile("cp.async.commit_group;" ::: "memory")
#define CP_WAIT1()  asm volatile("cp.async.wait_group 1;"  ::: "memory")
#define CP_WAIT0()  asm volatile("cp.async.wait_group 0;"  ::: "memory")

__device__ __forceinline__ void ldmx4(uint32_t* r, uint32_t addr) {
    asm volatile("ldmatrix.sync.aligned.m8n8.x4.shared.b16 {%0,%1,%2,%3}, [%4];"
                 : "=r"(r[0]), "=r"(r[1]), "=r"(r[2]), "=r"(r[3]) : "r"(addr));
}
__device__ __forceinline__ void mma_s8(int* c, const uint32_t* a,
                                       uint32_t b0, uint32_t b1) {
    asm volatile(
        "mma.sync.aligned.m16n8k32.row.col.s32.s8.s8.s32 "
        "{%0,%1,%2,%3}, {%4,%5,%6,%7}, {%8,%9}, {%0,%1,%2,%3};"
        : "+r"(c[0]), "+r"(c[1]), "+r"(c[2]), "+r"(c[3])
        : "r"(a[0]), "r"(a[1]), "r"(a[2]), "r"(a[3]), "r"(b0), "r"(b1));
}

__device__ __forceinline__ void split15(float v, float inv_s,
                                        int8_t& hi, int8_t& lo) {
    int xi = __float2int_rn(v * inv_s);
    xi = max(-32512, min(32512, xi));
    int h = (xi + 128) >> 8;            // round-to-nearest high byte
    hi = (int8_t)h;
    lo = (int8_t)(xi - (h << 8));
}

// ---------------------------------------------------------------------------
// scalar reset
// ---------------------------------------------------------------------------
__global__ void zero_scalars_kernel() { g_xmax_i = 0; g_wmax_i = 0; }

// ---------------------------------------------------------------------------
// |x| max reduction
// ---------------------------------------------------------------------------
__global__ void xmax_kernel(const float* __restrict__ x) {
    __shared__ float red[8];
    const size_t t = (size_t)blockIdx.x * 256 + threadIdx.x;
    float4 v = reinterpret_cast<const float4*>(x)[t];
    float m = fmaxf(fmaxf(fabsf(v.x), fabsf(v.y)), fmaxf(fabsf(v.z), fabsf(v.w)));
#pragma unroll
    for (int o = 16; o > 0; o >>= 1)
        m = fmaxf(m, __shfl_xor_sync(0xFFFFFFFF, m, o));
    if ((threadIdx.x & 31) == 0) red[threadIdx.x >> 5] = m;
    __syncthreads();
    if (threadIdx.x < 8) {
        m = red[threadIdx.x];
#pragma unroll
        for (int o = 4; o > 0; o >>= 1)
            m = fmaxf(m, __shfl_xor_sync(0xFF, m, o));
        if (threadIdx.x == 0) atomicMax(&g_xmax_i, __float_as_int(m));
    }
}

// ---------------------------------------------------------------------------
// quantize x -> (xh, xl)
// ---------------------------------------------------------------------------
__global__ void quantx_kernel(const float* __restrict__ x) {
    const float mx = __int_as_float(g_xmax_i);
    const float s = fmaxf(mx, 1e-30f) / 32512.0f;
    const float inv = 32512.0f / fmaxf(mx, 1e-30f);
    const size_t t = (size_t)blockIdx.x * 256 + threadIdx.x;
    float4 v = reinterpret_cast<const float4*>(x)[t];
    char4 h, l;
    split15(v.x, inv, (int8_t&)h.x, (int8_t&)l.x);
    split15(v.y, inv, (int8_t&)h.y, (int8_t&)l.y);
    split15(v.z, inv, (int8_t&)h.z, (int8_t&)l.z);
    split15(v.w, inv, (int8_t&)h.w, (int8_t&)l.w);
    reinterpret_cast<char4*>(g_xh)[t] = h;
    reinterpret_cast<char4*>(g_xl)[t] = l;
    if (blockIdx.x == 0 && threadIdx.x == 0) g_sx = s;
}

// ---------------------------------------------------------------------------
// W12[ia][jb][q] = sum_p c1[ia][p] * c2[jb][p][q].  CTA per jb, thread per ia.
// ---------------------------------------------------------------------------
__global__ void w12_kernel(const float* __restrict__ c1,
                           const float* __restrict__ c2) {
    __shared__ float sc2[1024];               // c2[jb][p][q]
    const int jb = blockIdx.x;
    const int tid = threadIdx.x;              // = ia

    reinterpret_cast<float4*>(sc2)[tid] =
        reinterpret_cast<const float4*>(c2 + (size_t)jb * 1024)[tid];

    float4 c1v[8];
    const float4* c1p = reinterpret_cast<const float4*>(c1 + tid * 32);
#pragma unroll
    for (int u = 0; u < 8; ++u) c1v[u] = c1p[u];
    __syncthreads();

    float4 acc[8];
#pragma unroll
    for (int u = 0; u < 8; ++u) acc[u] = make_float4(0.f, 0.f, 0.f, 0.f);

    const float4* sc2v = reinterpret_cast<const float4*>(sc2);
    const float* c1s = reinterpret_cast<const float*>(c1v);
#pragma unroll
    for (int p = 0; p < 32; ++p) {
        const float cp = c1s[p];
#pragma unroll
        for (int q4 = 0; q4 < 8; ++q4) {
            float4 w = sc2v[p * 8 + q4];      // broadcast across warp
            acc[q4].x = fmaf(cp, w.x, acc[q4].x);
            acc[q4].y = fmaf(cp, w.y, acc[q4].y);
            acc[q4].z = fmaf(cp, w.z, acc[q4].z);
            acc[q4].w = fmaf(cp, w.w, acc[q4].w);
        }
    }
    float4* outp = reinterpret_cast<float4*>(g_W12 + ((size_t)tid * 256 + jb) * 32);
#pragma unroll
    for (int u = 0; u < 8; ++u) outp[u] = acc[u];
}

// ---------------------------------------------------------------------------
// Assemble W^T fp32: CTA per (i,j), thread per (a,b).
//   Wf[(ab*16+c)][ij*16+kz] = sum_q W12[ia][jb][q] * c3[kz][c][q]
// Also tracks block |max| -> atomicMax.
// ---------------------------------------------------------------------------
__global__ void assemble_w_kernel(const float* __restrict__ c3) {
    __shared__ float sc3[8192];               // [kz][c][q] 32KB
    __shared__ float redmax[8];
    const int ij = blockIdx.x;
    const int tid = threadIdx.x;              // ab
    const int a = tid >> 4, b = tid & 15;
    const int i = ij >> 4, j = ij & 15;

    const float4* c3g = reinterpret_cast<const float4*>(c3);
    float4* sc3w = reinterpret_cast<float4*>(sc3);
#pragma unroll
    for (int u = 0; u < 8; ++u) sc3w[u * 256 + tid] = c3g[u * 256 + tid];

    float4 w12v[8];
    const float4* wp = reinterpret_cast<const float4*>(
        g_W12 + ((size_t)(i * 16 + a) * 256 + (j * 16 + b)) * 32);
#pragma unroll
    for (int u = 0; u < 8; ++u) w12v[u] = wp[u];
    __syncthreads();

    const float4* sc3v = reinterpret_cast<const float4*>(sc3);
    float m = 0.f;
#pragma unroll 1
    for (int c = 0; c < 16; ++c) {
        float acc[16];
#pragma unroll
        for (int kz = 0; kz < 16; ++kz) acc[kz] = 0.f;
#pragma unroll
        for (int q4 = 0; q4 < 8; ++q4) {
            const float4 w = w12v[q4];
#pragma unroll
            for (int kz = 0; kz < 16; ++kz) {
                float4 cv = sc3v[(kz * 16 + c) * 8 + q4];   // broadcast
                acc[kz] = fmaf(w.x, cv.x, acc[kz]);
                acc[kz] = fmaf(w.y, cv.y, acc[kz]);
                acc[kz] = fmaf(w.z, cv.z, acc[kz]);
                acc[kz] = fmaf(w.w, cv.w, acc[kz]);
            }
        }
        float* dst = g_Wf + (size_t)(tid * 16 + c) * KDIM + ij * 16;
#pragma unroll
        for (int u = 0; u < 4; ++u) {
            float4 o = make_float4(acc[u * 4], acc[u * 4 + 1],
                                   acc[u * 4 + 2], acc[u * 4 + 3]);
            m = fmaxf(m, fmaxf(fmaxf(fabsf(o.x), fabsf(o.y)),
                               fmaxf(fabsf(o.z), fabsf(o.w))));
            reinterpret_cast<float4*>(dst)[u] = o;
        }
    }
#pragma unroll
    for (int o = 16; o > 0; o >>= 1)
        m = fmaxf(m, __shfl_xor_sync(0xFFFFFFFF, m, o));
    if ((tid & 31) == 0) redmax[tid >> 5] = m;
    __syncthreads();
    if (tid < 8) {
        m = redmax[tid];
#pragma unroll
        for (int o = 4; o > 0; o >>= 1)
            m = fmaxf(m, __shfl_xor_sync(0xFF, m, o));
        if (tid == 0) atomicMax(&g_wmax_i, __float_as_int(m));
    }
}

// ---------------------------------------------------------------------------
// quantize W -> (wh, wl)
// ---------------------------------------------------------------------------
__global__ void quantw_kernel() {
    const float mw = __int_as_float(g_wmax_i);
    const float s = fmaxf(mw, 1e-30f) / 32512.0f;
    const float inv = 32512.0f / fmaxf(mw, 1e-30f);
    const size_t t = (size_t)blockIdx.x * 256 + threadIdx.x;
    float4 v = reinterpret_cast<const float4*>(g_Wf)[t];
    char4 h, l;
    split15(v.x, inv, (int8_t&)h.x, (int8_t&)l.x);
    split15(v.y, inv, (int8_t&)h.y, (int8_t&)l.y);
    split15(v.z, inv, (int8_t&)h.z, (int8_t&)l.z);
    split15(v.w, inv, (int8_t&)h.w, (int8_t&)l.w);
    reinterpret_cast<char4*>(g_wh)[t] = h;
    reinterpret_cast<char4*>(g_wl)[t] = l;
    if (blockIdx.x == 0 && threadIdx.x == 0) g_sw = s;
}

// ---------------------------------------------------------------------------
// int8 GEMM: CTA tile 128x128, BK=64 (int8), 8 warps (2m x 4n), warp 64x32.
// SMEM rows 64B data padded to 80B (conflict-free ldmatrix).
// 2 products worth of accumulators: hh and cross (xh*wl + xl*wh).
// ---------------------------------------------------------------------------
#define BM 128
#define BN 128
#define ROWB 80
#define ARR_BYTES (128 * ROWB)       // 10240
#define STAGE_BYTES (4 * ARR_BYTES)  // xh | xl | wh | wl
#define DYN_BYTES (2 * STAGE_BYTES)  // 81920

__global__ __launch_bounds__(256, 1)
void tt_gemm_s8(const float* __restrict__ bias, float* __restrict__ C) {
    extern __shared__ __align__(16) char dyn[];
    const uint32_t dynU = smem_u32(dyn);

    const int tid = threadIdx.x;
    const int wid = tid >> 5;
    const int lid = tid & 31;
    const int warp_m = wid & 1;
    const int warp_n = wid >> 1;
    const int m0 = blockIdx.y * BM;
    const int n0 = blockIdx.x * BN;

    const char* xh = (const char*)g_xh;
    const char* xl = (const char*)g_xl;
    const char* wh = (const char*)g_wh;
    const char* wl = (const char*)g_wl;

    // loader: rows of 64B, 4x16B chunks -> 2 chunks/thread/array
    const int r0c = tid >> 2, ch0 = (tid & 3) * 16;
    const int r1c = (256 + tid) >> 2, ch1 = ((256 + tid) & 3) * 16;
    const uint32_t s0 = (uint32_t)(r0c * ROWB + ch0);
    const uint32_t s1 = (uint32_t)(r1c * ROWB + ch1);
    const size_t gA0 = (size_t)(m0 + r0c) * KDIM + ch0;
    const size_t gA1 = (size_t)(m0 + r1c) * KDIM + ch1;
    const size_t gB0 = (size_t)(n0 + r0c) * KDIM + ch0;
    const size_t gB1 = (size_t)(n0 + r1c) * KDIM + ch1;

    int acc_hh[4][4][4];
    int acc_cx[4][4][4];
#pragma unroll
    for (int a = 0; a < 4; ++a)
#pragma unroll
        for (int b = 0; b < 4; ++b)
#pragma unroll
            for (int c = 0; c < 4; ++c) { acc_hh[a][b][c] = 0; acc_cx[a][b][c] = 0; }

    const uint32_t lmRow = (uint32_t)(lid & 15);
    const uint32_t lmCol = (uint32_t)((lid >> 4) * 16);
    const uint32_t aLM = (uint32_t)((warp_m * 64 + lmRow) * ROWB) + lmCol;
    const uint32_t bLM = (uint32_t)((warp_n * 32 + lmRow) * ROWB) + lmCol;

    auto load_stage = [&](int kt) {
        const uint32_t sb = dynU + (uint32_t)(kt & 1) * STAGE_BYTES;
        const size_t ko = (size_t)kt * 64;      // 64 int8 k's per stage
        cp_async16(sb + s0,                 xh + gA0 + ko);
        cp_async16(sb + s1,                 xh + gA1 + ko);
        cp_async16(sb + ARR_BYTES + s0,     xl + gA0 + ko);
        cp_async16(sb + ARR_BYTES + s1,     xl + gA1 + ko);
        cp_async16(sb + 2 * ARR_BYTES + s0, wh + gB0 + ko);
        cp_async16(sb + 2 * ARR_BYTES + s1, wh + gB1 + ko);
        cp_async16(sb + 3 * ARR_BYTES + s0, wl + gB0 + ko);
        cp_async16(sb + 3 * ARR_BYTES + s1, wl + gB1 + ko);
    };

    load_stage(0);
    CP_COMMIT();

    const int numK = KDIM / 64;                 // 64 stages
    for (int kt = 0; kt < numK; ++kt) {
        if (kt + 1 < numK) {
            load_stage(kt + 1);
            CP_COMMIT();
            CP_WAIT1();
        } else {
            CP_WAIT0();
        }
        __syncthreads();

        const uint32_t sb = dynU + (uint32_t)(kt & 1) * STAGE_BYTES;
        const uint32_t aB = sb + aLM;
        const uint32_t bB = sb + 2 * ARR_BYTES + bLM;

#pragma unroll
        for (int ks = 0; ks < 2; ++ks) {            // two k32 steps
            const uint32_t kb = (uint32_t)(ks * 32);
            uint32_t ah[4][4], al[4][4];
#pragma unroll
            for (int mt = 0; mt < 4; ++mt) {
                ldmx4(ah[mt], aB + (uint32_t)(mt * 16 * ROWB) + kb);
                ldmx4(al[mt], aB + ARR_BYTES + (uint32_t)(mt * 16 * ROWB) + kb);
            }
            uint32_t bh[2][4], bl[2][4];
#pragma unroll
            for (int bt = 0; bt < 2; ++bt) {
                ldmx4(bh[bt], bB + (uint32_t)(bt * 16 * ROWB) + kb);
                ldmx4(bl[bt], bB + ARR_BYTES + (uint32_t)(bt * 16 * ROWB) + kb);
            }
#pragma unroll
            for (int mt = 0; mt < 4; ++mt) {
#pragma unroll
                for (int nt = 0; nt < 4; ++nt) {
                    const int bt = nt >> 1, o = nt & 1;
                    mma_s8(acc_hh[mt][nt], ah[mt], bh[bt][o], bh[bt][o + 2]);
                    mma_s8(acc_cx[mt][nt], ah[mt], bl[bt][o], bl[bt][o + 2]);
                    mma_s8(acc_cx[mt][nt], al[mt], bh[bt][o], bh[bt][o + 2]);
                }
            }
        }
        __syncthreads();
    }

    // epilogue: dequant + bias + relu
    const float sxw = g_sx * g_sw;
    const int g = lid >> 2, t4 = lid & 3;
    float bb[4][2];
#pragma unroll
    for (int nt = 0; nt < 4; ++nt) {
        const int col = n0 + warp_n * 32 + nt * 8 + t4 * 2;
        bb[nt][0] = bias[col];
        bb[nt][1] = bias[col + 1];
    }
#pragma unroll
    for (int mt = 0; mt < 4; ++mt) {
        const int row = m0 + warp_m * 64 + mt * 16 + g;
#pragma unroll
        for (int nt = 0; nt < 4; ++nt) {
            const int col = n0 + warp_n * 32 + nt * 8 + t4 * 2;
            float2 v0, v1;
            v0.x = fmaxf(fmaf(sxw, 65536.f * (float)acc_hh[mt][nt][0]
                                   + 256.f * (float)acc_cx[mt][nt][0], bb[nt][0]), 0.f);
            v0.y = fmaxf(fmaf(sxw, 65536.f * (float)acc_hh[mt][nt][1]
                                   + 256.f * (float)acc_cx[mt][nt][1], bb[nt][1]), 0.f);
            v1.x = fmaxf(fmaf(sxw, 65536.f * (float)acc_hh[mt][nt][2]
                                   + 256.f * (float)acc_cx[mt][nt][2], bb[nt][0]), 0.f);
            v1.y = fmaxf(fmaf(sxw, 65536.f * (float)acc_hh[mt][nt][3]
                                   + 256.f * (float)acc_cx[mt][nt][3], bb[nt][1]), 0.f);
            *reinterpret_cast<float2*>(&C[(size_t)row * NDIM + col]) = v0;
            *reinterpret_cast<float2*>(&C[(size_t)(row + 8) * NDIM + col]) = v1;
        }
    }
}

// ---------------------------------------------------------------------------
// Launch
// ---------------------------------------------------------------------------
extern "C" void kernel_launch(void* const* d_in, const int* in_sizes, int n_in,
                              void* d_out, int out_size) {
    const float* x    = (const float*)d_in[0];
    const float* c1   = (const float*)d_in[1];
    const float* c2   = (const float*)d_in[2];
    const float* c3   = (const float*)d_in[3];
    const float* bias = (const float*)d_in[4];
    float* out = (float*)d_out;
    (void)in_sizes; (void)n_in; (void)out_size;

    cudaFuncSetAttribute(tt_gemm_s8,
                         cudaFuncAttributeMaxDynamicSharedMemorySize, DYN_BYTES);

    zero_scalars_kernel<<<1, 1>>>();
    xmax_kernel<<<(BATCH * KDIM) / (4 * 256), 256>>>(x);
    quantx_kernel<<<(BATCH * KDIM) / (4 * 256), 256>>>(x);
    w12_kernel<<<256, 256>>>(c1, c2);
    assemble_w_kernel<<<256, 256>>>(c3);
    quantw_kernel<<<((size_t)NDIM * KDIM) / (4 * 256), 256>>>();

    dim3 grid(NDIM / BN, BATCH / BM);   // (32, 16) = 512 CTAs
    tt_gemm_s8<<<grid, 256, DYN_BYTES>>>(bias, out);
}

// round 5
// speedup vs baseline: 3.0645x; 3.0645x over previous
#include <cuda_runtime.h>
#include <cuda_fp16.h>
#include <cstdint>

// ============================================================================
// TensorDense via explicit-W:  out = relu(x @ W + bias)
//   W[(i,j,k),(a,b,c)] = sum_q (sum_p c1[i,a,p] c2[j,b,p,q]) c3[k,c,q]
// GEMM on legacy tensor cores, fp16 2-product split precision:
//   x = xh + xl (both fp16; x exact to ~2^-22),  W -> fp16 (error 2^-11 RMS)
//   out = xh*wh + xl*wh   (single W array, shared B fragments, fp32 accum)
// ============================================================================

#define MODE 16
#define KDIM 4096
#define NDIM 4096
#define BATCH 2048

__device__ float  g_W12[256 * 256 * 32];            // [ia][jb][q]  8MB
__device__ __half g_xh[(size_t)BATCH * KDIM];
__device__ __half g_xl[(size_t)BATCH * KDIM];
__device__ __half g_wh[(size_t)NDIM * KDIM];        // W^T [n][k], fp16

// ---------------------------------------------------------------------------
// helpers (all sm_80/sm_90-era; no arch-'a' features — ptxas targets sm_103)
// ---------------------------------------------------------------------------
__device__ __forceinline__ uint32_t smem_u32(const void* p) {
    uint32_t a;
    asm("{ .reg .u64 t; cvta.to.shared.u64 t, %1; cvt.u32.u64 %0, t; }"
        : "=r"(a) : "l"(p));
    return a;
}
__device__ __forceinline__ void cp_async16(uint32_t s, const void* g) {
    asm volatile("cp.async.cg.shared.global [%0], [%1], 16;" :: "r"(s), "l"(g));
}
#define CP_COMMIT() asm volatile("cp.async.commit_group;" ::: "memory")
#define CP_WAIT1()  asm volatile("cp.async.wait_group 1;"  ::: "memory")
#define CP_WAIT0()  asm volatile("cp.async.wait_group 0;"  ::: "memory")

__device__ __forceinline__ void ldmx4(uint32_t* r, uint32_t addr) {
    asm volatile("ldmatrix.sync.aligned.m8n8.x4.shared.b16 {%0,%1,%2,%3}, [%4];"
                 : "=r"(r[0]), "=r"(r[1]), "=r"(r[2]), "=r"(r[3]) : "r"(addr));
}
__device__ __forceinline__ void mma_f16(float* c, const uint32_t* a,
                                        uint32_t b0, uint32_t b1) {
    asm volatile(
        "mma.sync.aligned.m16n8k16.row.col.f32.f16.f16.f32 "
        "{%0,%1,%2,%3}, {%4,%5,%6,%7}, {%8,%9}, {%0,%1,%2,%3};"
        : "+f"(c[0]), "+f"(c[1]), "+f"(c[2]), "+f"(c[3])
        : "r"(a[0]), "r"(a[1]), "r"(a[2]), "r"(a[3]), "r"(b0), "r"(b1));
}

// ---------------------------------------------------------------------------
// Kernel 1: split x into fp16 hi/lo.
// ---------------------------------------------------------------------------
__global__ void split_x_kernel(const float* __restrict__ x) {
    const size_t t = (size_t)blockIdx.x * 256 + threadIdx.x;
    float4 v = reinterpret_cast<const float4*>(x)[t];
    __half2 h01 = __floats2half2_rn(v.x, v.y);
    __half2 h23 = __floats2half2_rn(v.z, v.w);
    float2 f01 = __half22float2(h01);
    float2 f23 = __half22float2(h23);
    __half2 l01 = __floats2half2_rn(v.x - f01.x, v.y - f01.y);
    __half2 l23 = __floats2half2_rn(v.z - f23.x, v.w - f23.y);
    reinterpret_cast<__half2*>(g_xh)[t * 2 + 0] = h01;
    reinterpret_cast<__half2*>(g_xh)[t * 2 + 1] = h23;
    reinterpret_cast<__half2*>(g_xl)[t * 2 + 0] = l01;
    reinterpret_cast<__half2*>(g_xl)[t * 2 + 1] = l23;
}

// ---------------------------------------------------------------------------
// Kernel 2: W12[ia][jb][q] = sum_p c1[ia][p] * c2[jb][p][q]. CTA/jb, thr/ia.
// ---------------------------------------------------------------------------
__global__ void w12_kernel(const float* __restrict__ c1,
                           const float* __restrict__ c2) {
    __shared__ float sc2[1024];
    const int jb = blockIdx.x;
    const int tid = threadIdx.x;              // = ia

    reinterpret_cast<float4*>(sc2)[tid] =
        reinterpret_cast<const float4*>(c2 + (size_t)jb * 1024)[tid];

    float4 c1v[8];
    const float4* c1p = reinterpret_cast<const float4*>(c1 + tid * 32);
#pragma unroll
    for (int u = 0; u < 8; ++u) c1v[u] = c1p[u];
    __syncthreads();

    float4 acc[8];
#pragma unroll
    for (int u = 0; u < 8; ++u) acc[u] = make_float4(0.f, 0.f, 0.f, 0.f);

    const float4* sc2v = reinterpret_cast<const float4*>(sc2);
    const float* c1s = reinterpret_cast<const float*>(c1v);
#pragma unroll
    for (int p = 0; p < 32; ++p) {
        const float cp = c1s[p];
#pragma unroll
        for (int q4 = 0; q4 < 8; ++q4) {
            float4 w = sc2v[p * 8 + q4];
            acc[q4].x = fmaf(cp, w.x, acc[q4].x);
            acc[q4].y = fmaf(cp, w.y, acc[q4].y);
            acc[q4].z = fmaf(cp, w.z, acc[q4].z);
            acc[q4].w = fmaf(cp, w.w, acc[q4].w);
        }
    }
    float4* outp = reinterpret_cast<float4*>(g_W12 + ((size_t)tid * 256 + jb) * 32);
#pragma unroll
    for (int u = 0; u < 8; ++u) outp[u] = acc[u];
}

// ---------------------------------------------------------------------------
// Kernel 3: assemble W^T in fp16. CTA per (i,j), thread per (a,b).
//   wh[(ab*16+c)][ij*16+kz] = fp16( sum_q W12[ia][jb][q] * c3[kz][c][q] )
// ---------------------------------------------------------------------------
__global__ void assemble_w_kernel(const float* __restrict__ c3) {
    __shared__ float sc3[8192];               // [kz][c][q] 32KB
    const int ij = blockIdx.x;
    const int tid = threadIdx.x;              // ab
    const int a = tid >> 4, b = tid & 15;
    const int i = ij >> 4, j = ij & 15;

    const float4* c3g = reinterpret_cast<const float4*>(c3);
    float4* sc3w = reinterpret_cast<float4*>(sc3);
#pragma unroll
    for (int u = 0; u < 8; ++u) sc3w[u * 256 + tid] = c3g[u * 256 + tid];

    float4 w12v[8];
    const float4* wp = reinterpret_cast<const float4*>(
        g_W12 + ((size_t)(i * 16 + a) * 256 + (j * 16 + b)) * 32);
#pragma unroll
    for (int u = 0; u < 8; ++u) w12v[u] = wp[u];
    __syncthreads();

    const float4* sc3v = reinterpret_cast<const float4*>(sc3);
#pragma unroll 1
    for (int c = 0; c < 16; ++c) {
        float acc[16];
#pragma unroll
        for (int kz = 0; kz < 16; ++kz) acc[kz] = 0.f;
#pragma unroll
        for (int q4 = 0; q4 < 8; ++q4) {
            const float4 w = w12v[q4];
#pragma unroll
            for (int kz = 0; kz < 16; ++kz) {
                float4 cv = sc3v[(kz * 16 + c) * 8 + q4];   // warp broadcast
                acc[kz] = fmaf(w.x, cv.x, acc[kz]);
                acc[kz] = fmaf(w.y, cv.y, acc[kz]);
                acc[kz] = fmaf(w.z, cv.z, acc[kz]);
                acc[kz] = fmaf(w.w, cv.w, acc[kz]);
            }
        }
        // 16 halves = 32B contiguous along k
        __half2 hv[8];
#pragma unroll
        for (int u = 0; u < 8; ++u)
            hv[u] = __floats2half2_rn(acc[u * 2], acc[u * 2 + 1]);
        __half* dst = g_wh + (size_t)(tid * 16 + c) * KDIM + ij * 16;
        reinterpret_cast<uint4*>(dst)[0] = reinterpret_cast<uint4*>(hv)[0];
        reinterpret_cast<uint4*>(dst)[1] = reinterpret_cast<uint4*>(hv)[1];
    }
}

// ---------------------------------------------------------------------------
// Kernel 4: fp16 2-product GEMM.
// CTA tile 128x128, BK=32, 8 warps (2m x 4n), warp tile 64x32.
// SMEM rows 64B data padded to 80B (conflict-free ldmatrix).
// ---------------------------------------------------------------------------
#define BM 128
#define BN 128
#define ROWB 80
#define ARR_BYTES (128 * ROWB)       // 10240
#define STAGE_BYTES (3 * ARR_BYTES)  // xh | xl | wh = 30720
#define DYN_BYTES (2 * STAGE_BYTES)  // 61440

__global__ __launch_bounds__(256, 1)
void tt_gemm_f16x2(const float* __restrict__ bias, float* __restrict__ C) {
    extern __shared__ __align__(16) char dyn[];
    const uint32_t dynU = smem_u32(dyn);

    const int tid = threadIdx.x;
    const int wid = tid >> 5;
    const int lid = tid & 31;
    const int warp_m = wid & 1;      // 64 rows each
    const int warp_n = wid >> 1;     // 32 cols each
    const int m0 = blockIdx.y * BM;
    const int n0 = blockIdx.x * BN;

    const char* xh = (const char*)g_xh;
    const char* xl = (const char*)g_xl;
    const char* wh = (const char*)g_wh;

    // loader mapping: 128 rows x 64B (4 chunks of 16B); 2 chunks/thread/array
    const int r0c = tid >> 2, ch0 = (tid & 3) * 16;
    const int r1c = (256 + tid) >> 2, ch1 = ((256 + tid) & 3) * 16;
    const uint32_t s0 = (uint32_t)(r0c * ROWB + ch0);
    const uint32_t s1 = (uint32_t)(r1c * ROWB + ch1);
    const size_t gA0 = (size_t)(m0 + r0c) * (KDIM * 2) + ch0;
    const size_t gA1 = (size_t)(m0 + r1c) * (KDIM * 2) + ch1;
    const size_t gB0 = (size_t)(n0 + r0c) * (KDIM * 2) + ch0;
    const size_t gB1 = (size_t)(n0 + r1c) * (KDIM * 2) + ch1;

    float acc[4][4][4];
#pragma unroll
    for (int a = 0; a < 4; ++a)
#pragma unroll
        for (int b = 0; b < 4; ++b)
#pragma unroll
            for (int c = 0; c < 4; ++c) acc[a][b][c] = 0.f;

    const uint32_t lmRow = (uint32_t)(lid & 15);
    const uint32_t lmCol = (uint32_t)((lid >> 4) * 16);
    const uint32_t aLM = (uint32_t)((warp_m * 64 + lmRow) * ROWB) + lmCol;
    const uint32_t bLM = (uint32_t)((warp_n * 32 + lmRow) * ROWB) + lmCol;

    auto load_stage = [&](int kt) {
        const uint32_t sb = dynU + (uint32_t)(kt & 1) * STAGE_BYTES;
        const size_t ko = (size_t)kt * 64;   // 32 halves = 64B along k
        cp_async16(sb + s0,                 xh + gA0 + ko);
        cp_async16(sb + s1,                 xh + gA1 + ko);
        cp_async16(sb + ARR_BYTES + s0,     xl + gA0 + ko);
        cp_async16(sb + ARR_BYTES + s1,     xl + gA1 + ko);
        cp_async16(sb + 2 * ARR_BYTES + s0, wh + gB0 + ko);
        cp_async16(sb + 2 * ARR_BYTES + s1, wh + gB1 + ko);
    };

    load_stage(0);
    CP_COMMIT();

    const int numK = KDIM / 32;      // 128 stages
    for (int kt = 0; kt < numK; ++kt) {
        if (kt + 1 < numK) {
            load_stage(kt + 1);
            CP_COMMIT();
            CP_WAIT1();
        } else {
            CP_WAIT0();
        }
        __syncthreads();

        const uint32_t sb = dynU + (uint32_t)(kt & 1) * STAGE_BYTES;
        const uint32_t aB = sb + aLM;
        const uint32_t bB = sb + 2 * ARR_BYTES + bLM;

#pragma unroll
        for (int ks = 0; ks < 2; ++ks) {             // two k16 steps
            const uint32_t kb = (uint32_t)(ks * 32); // 16 halves = 32B
            uint32_t ah[4][4], al[4][4];
#pragma unroll
            for (int mt = 0; mt < 4; ++mt) {
                ldmx4(ah[mt], aB + (uint32_t)(mt * 16 * ROWB) + kb);
                ldmx4(al[mt], aB + ARR_BYTES + (uint32_t)(mt * 16 * ROWB) + kb);
            }
            uint32_t bh[2][4];
#pragma unroll
            for (int bt = 0; bt < 2; ++bt)
                ldmx4(bh[bt], bB + (uint32_t)(bt * 16 * ROWB) + kb);
#pragma unroll
            for (int mt = 0; mt < 4; ++mt) {
#pragma unroll
                for (int nt = 0; nt < 4; ++nt) {
                    const int bt = nt >> 1, o = nt & 1;
                    mma_f16(acc[mt][nt], ah[mt], bh[bt][o], bh[bt][o + 2]);
                    mma_f16(acc[mt][nt], al[mt], bh[bt][o], bh[bt][o + 2]);
                }
            }
        }
        __syncthreads();
    }

    // epilogue: bias + relu, float2 stores
    const int g = lid >> 2, t4 = lid & 3;
    float bb[4][2];
#pragma unroll
    for (int nt = 0; nt < 4; ++nt) {
        const int col = n0 + warp_n * 32 + nt * 8 + t4 * 2;
        bb[nt][0] = bias[col];
        bb[nt][1] = bias[col + 1];
    }
#pragma unroll
    for (int mt = 0; mt < 4; ++mt) {
        const int row = m0 + warp_m * 64 + mt * 16 + g;
#pragma unroll
        for (int nt = 0; nt < 4; ++nt) {
            const int col = n0 + warp_n * 32 + nt * 8 + t4 * 2;
            float2 v0, v1;
            v0.x = fmaxf(acc[mt][nt][0] + bb[nt][0], 0.f);
            v0.y = fmaxf(acc[mt][nt][1] + bb[nt][1], 0.f);
            v1.x = fmaxf(acc[mt][nt][2] + bb[nt][0], 0.f);
            v1.y = fmaxf(acc[mt][nt][3] + bb[nt][1], 0.f);
            *reinterpret_cast<float2*>(&C[(size_t)row * NDIM + col]) = v0;
            *reinterpret_cast<float2*>(&C[(size_t)(row + 8) * NDIM + col]) = v1;
        }
    }
}

// ---------------------------------------------------------------------------
// Launch
// ---------------------------------------------------------------------------
extern "C" void kernel_launch(void* const* d_in, const int* in_sizes, int n_in,
                              void* d_out, int out_size) {
    const float* x    = (const float*)d_in[0];
    const float* c1   = (const float*)d_in[1];
    const float* c2   = (const float*)d_in[2];
    const float* c3   = (const float*)d_in[3];
    const float* bias = (const float*)d_in[4];
    float* out = (float*)d_out;
    (void)in_sizes; (void)n_in; (void)out_size;

    cudaFuncSetAttribute(tt_gemm_f16x2,
                         cudaFuncAttributeMaxDynamicSharedMemorySize, DYN_BYTES);

    split_x_kernel<<<(BATCH * KDIM) / (4 * 256), 256>>>(x);
    w12_kernel<<<256, 256>>>(c1, c2);
    assemble_w_kernel<<<256, 256>>>(c3);

    dim3 grid(NDIM / BN, BATCH / BM);   // (32, 16) = 512 CTAs
    tt_gemm_f16x2<<<grid, 256, DYN_BYTES>>>(bias, out);
}

// round 6
// speedup vs baseline: 5.5753x; 1.8193x over previous
#include <cuda_runtime.h>
#include <cuda_fp16.h>
#include <cstdint>

// ============================================================================
// TensorDense via explicit-W:  out = relu(x @ W + bias)
//   W[(i,j,k),(a,b,c)] = sum_q (sum_p c1[i,a,p] c2[j,b,p,q]) c3[k,c,q]
// Single-product fp16 GEMM on legacy tensor cores (mma.sync, fp32 accum):
//   x -> fp16, W -> fp16;  error ~ 2.9e-4 RMS (quadrature of two roundings),
//   3.4x margin vs the 1e-3 gate. 4-stage cp.async pipeline, 2 CTAs/SM.
// ============================================================================

#define MODE 16
#define KDIM 4096
#define NDIM 4096
#define BATCH 2048

__device__ float  g_W12[256 * 256 * 32];            // [ia][jb][q]  8MB
__device__ __half g_xh[(size_t)BATCH * KDIM];
__device__ __half g_wh[(size_t)NDIM * KDIM];        // W^T [n][k], fp16

// ---------------------------------------------------------------------------
// helpers (sm_80/sm_90-era only; ptxas targets bare sm_103)
// ---------------------------------------------------------------------------
__device__ __forceinline__ uint32_t smem_u32(const void* p) {
    uint32_t a;
    asm("{ .reg .u64 t; cvta.to.shared.u64 t, %1; cvt.u32.u64 %0, t; }"
        : "=r"(a) : "l"(p));
    return a;
}
__device__ __forceinline__ void cp_async16(uint32_t s, const void* g) {
    asm volatile("cp.async.cg.shared.global [%0], [%1], 16;" :: "r"(s), "l"(g));
}
#define CP_COMMIT() asm volatile("cp.async.commit_group;" ::: "memory")
#define CP_WAIT2()  asm volatile("cp.async.wait_group 2;"  ::: "memory")

__device__ __forceinline__ void ldmx4(uint32_t* r, uint32_t addr) {
    asm volatile("ldmatrix.sync.aligned.m8n8.x4.shared.b16 {%0,%1,%2,%3}, [%4];"
                 : "=r"(r[0]), "=r"(r[1]), "=r"(r[2]), "=r"(r[3]) : "r"(addr));
}
__device__ __forceinline__ void mma_f16(float* c, const uint32_t* a,
                                        uint32_t b0, uint32_t b1) {
    asm volatile(
        "mma.sync.aligned.m16n8k16.row.col.f32.f16.f16.f32 "
        "{%0,%1,%2,%3}, {%4,%5,%6,%7}, {%8,%9}, {%0,%1,%2,%3};"
        : "+f"(c[0]), "+f"(c[1]), "+f"(c[2]), "+f"(c[3])
        : "r"(a[0]), "r"(a[1]), "r"(a[2]), "r"(a[3]), "r"(b0), "r"(b1));
}

// ---------------------------------------------------------------------------
// Kernel 1: x -> fp16
// ---------------------------------------------------------------------------
__global__ void cvt_x_kernel(const float* __restrict__ x) {
    const size_t t = (size_t)blockIdx.x * 256 + threadIdx.x;
    float4 v = reinterpret_cast<const float4*>(x)[t];
    __half2 h01 = __floats2half2_rn(v.x, v.y);
    __half2 h23 = __floats2half2_rn(v.z, v.w);
    reinterpret_cast<__half2*>(g_xh)[t * 2 + 0] = h01;
    reinterpret_cast<__half2*>(g_xh)[t * 2 + 1] = h23;
}

// ---------------------------------------------------------------------------
// Kernel 2: W12[ia][jb][q] = sum_p c1[ia][p] * c2[jb][p][q]. CTA/jb, thr/ia.
// ---------------------------------------------------------------------------
__global__ void w12_kernel(const float* __restrict__ c1,
                           const float* __restrict__ c2) {
    __shared__ float sc2[1024];
    const int jb = blockIdx.x;
    const int tid = threadIdx.x;              // = ia

    reinterpret_cast<float4*>(sc2)[tid] =
        reinterpret_cast<const float4*>(c2 + (size_t)jb * 1024)[tid];

    float4 c1v[8];
    const float4* c1p = reinterpret_cast<const float4*>(c1 + tid * 32);
#pragma unroll
    for (int u = 0; u < 8; ++u) c1v[u] = c1p[u];
    __syncthreads();

    float4 acc[8];
#pragma unroll
    for (int u = 0; u < 8; ++u) acc[u] = make_float4(0.f, 0.f, 0.f, 0.f);

    const float4* sc2v = reinterpret_cast<const float4*>(sc2);
    const float* c1s = reinterpret_cast<const float*>(c1v);
#pragma unroll
    for (int p = 0; p < 32; ++p) {
        const float cp = c1s[p];
#pragma unroll
        for (int q4 = 0; q4 < 8; ++q4) {
            float4 w = sc2v[p * 8 + q4];
            acc[q4].x = fmaf(cp, w.x, acc[q4].x);
            acc[q4].y = fmaf(cp, w.y, acc[q4].y);
            acc[q4].z = fmaf(cp, w.z, acc[q4].z);
            acc[q4].w = fmaf(cp, w.w, acc[q4].w);
        }
    }
    float4* outp = reinterpret_cast<float4*>(g_W12 + ((size_t)tid * 256 + jb) * 32);
#pragma unroll
    for (int u = 0; u < 8; ++u) outp[u] = acc[u];
}

// ---------------------------------------------------------------------------
// Kernel 3: assemble W^T in fp16. CTA per (i,j), thread per (a,b).
// ---------------------------------------------------------------------------
__global__ void assemble_w_kernel(const float* __restrict__ c3) {
    __shared__ float sc3[8192];               // [kz][c][q] 32KB
    const int ij = blockIdx.x;
    const int tid = threadIdx.x;              // ab
    const int a = tid >> 4, b = tid & 15;
    const int i = ij >> 4, j = ij & 15;

    const float4* c3g = reinterpret_cast<const float4*>(c3);
    float4* sc3w = reinterpret_cast<float4*>(sc3);
#pragma unroll
    for (int u = 0; u < 8; ++u) sc3w[u * 256 + tid] = c3g[u * 256 + tid];

    float4 w12v[8];
    const float4* wp = reinterpret_cast<const float4*>(
        g_W12 + ((size_t)(i * 16 + a) * 256 + (j * 16 + b)) * 32);
#pragma unroll
    for (int u = 0; u < 8; ++u) w12v[u] = wp[u];
    __syncthreads();

    const float4* sc3v = reinterpret_cast<const float4*>(sc3);
#pragma unroll 1
    for (int c = 0; c < 16; ++c) {
        float acc[16];
#pragma unroll
        for (int kz = 0; kz < 16; ++kz) acc[kz] = 0.f;
#pragma unroll
        for (int q4 = 0; q4 < 8; ++q4) {
            const float4 w = w12v[q4];
#pragma unroll
            for (int kz = 0; kz < 16; ++kz) {
                float4 cv = sc3v[(kz * 16 + c) * 8 + q4];   // warp broadcast
                acc[kz] = fmaf(w.x, cv.x, acc[kz]);
                acc[kz] = fmaf(w.y, cv.y, acc[kz]);
                acc[kz] = fmaf(w.z, cv.z, acc[kz]);
                acc[kz] = fmaf(w.w, cv.w, acc[kz]);
            }
        }
        __half2 hv[8];
#pragma unroll
        for (int u = 0; u < 8; ++u)
            hv[u] = __floats2half2_rn(acc[u * 2], acc[u * 2 + 1]);
        __half* dst = g_wh + (size_t)(tid * 16 + c) * KDIM + ij * 16;
        reinterpret_cast<uint4*>(dst)[0] = reinterpret_cast<uint4*>(hv)[0];
        reinterpret_cast<uint4*>(dst)[1] = reinterpret_cast<uint4*>(hv)[1];
    }
}

// ---------------------------------------------------------------------------
// Kernel 4: single-product fp16 GEMM.
// CTA tile 128x128, BK=32, 8 warps (2m x 4n), warp tile 64x32.
// 4-stage cp.async pipeline, ONE __syncthreads per stage, 2 CTAs/SM.
// SMEM rows 64B data padded to 80B (conflict-free ldmatrix).
// ---------------------------------------------------------------------------
#define BM 128
#define BN 128
#define ROWB 80
#define ARR_BYTES (128 * ROWB)       // 10240
#define STAGE_BYTES (2 * ARR_BYTES)  // xh | wh = 20480
#define STAGES 4
#define DYN_BYTES (STAGES * STAGE_BYTES)  // 81920

__global__ __launch_bounds__(256, 2)
void tt_gemm_f16(const float* __restrict__ bias, float* __restrict__ C) {
    extern __shared__ __align__(16) char dyn[];
    const uint32_t dynU = smem_u32(dyn);

    const int tid = threadIdx.x;
    const int wid = tid >> 5;
    const int lid = tid & 31;
    const int warp_m = wid & 1;      // 64 rows each
    const int warp_n = wid >> 1;     // 32 cols each
    const int m0 = blockIdx.y * BM;
    const int n0 = blockIdx.x * BN;

    const char* xh = (const char*)g_xh;
    const char* wh = (const char*)g_wh;

    // loader mapping: 128 rows x 64B (4 chunks of 16B); 2 chunks/thread/array
    const int r0c = tid >> 2, ch0 = (tid & 3) * 16;
    const int r1c = (256 + tid) >> 2, ch1 = ((256 + tid) & 3) * 16;
    const uint32_t s0 = (uint32_t)(r0c * ROWB + ch0);
    const uint32_t s1 = (uint32_t)(r1c * ROWB + ch1);
    const size_t gA0 = (size_t)(m0 + r0c) * (KDIM * 2) + ch0;
    const size_t gA1 = (size_t)(m0 + r1c) * (KDIM * 2) + ch1;
    const size_t gB0 = (size_t)(n0 + r0c) * (KDIM * 2) + ch0;
    const size_t gB1 = (size_t)(n0 + r1c) * (KDIM * 2) + ch1;

    float acc[4][4][4];
#pragma unroll
    for (int a = 0; a < 4; ++a)
#pragma unroll
        for (int b = 0; b < 4; ++b)
#pragma unroll
            for (int c = 0; c < 4; ++c) acc[a][b][c] = 0.f;

    const uint32_t lmRow = (uint32_t)(lid & 15);
    const uint32_t lmCol = (uint32_t)((lid >> 4) * 16);
    const uint32_t aLM = (uint32_t)((warp_m * 64 + lmRow) * ROWB) + lmCol;
    const uint32_t bLM = (uint32_t)((warp_n * 32 + lmRow) * ROWB) + lmCol;

    auto load_stage = [&](int kt) {
        const uint32_t sb = dynU + (uint32_t)(kt & (STAGES - 1)) * STAGE_BYTES;
        const size_t ko = (size_t)kt * 64;   // 32 halves = 64B along k
        cp_async16(sb + s0,             xh + gA0 + ko);
        cp_async16(sb + s1,             xh + gA1 + ko);
        cp_async16(sb + ARR_BYTES + s0, wh + gB0 + ko);
        cp_async16(sb + ARR_BYTES + s1, wh + gB1 + ko);
    };

    // preload stages 0..STAGES-2
#pragma unroll
    for (int p = 0; p < STAGES - 1; ++p) { load_stage(p); CP_COMMIT(); }

    const int numK = KDIM / 32;      // 128 stages
    for (int kt = 0; kt < numK; ++kt) {
        CP_WAIT2();                  // stage kt arrived (<=2 groups pending)
        __syncthreads();             // publish stage kt; all warps done with kt-1

        if (kt + STAGES - 1 < numK) load_stage(kt + STAGES - 1);
        CP_COMMIT();                 // keep group accounting uniform

        const uint32_t sb = dynU + (uint32_t)(kt & (STAGES - 1)) * STAGE_BYTES;
        const uint32_t aB = sb + aLM;
        const uint32_t bB = sb + ARR_BYTES + bLM;

#pragma unroll
        for (int ks = 0; ks < 2; ++ks) {             // two k16 steps
            const uint32_t kb = (uint32_t)(ks * 32); // 16 halves = 32B
            uint32_t ah[4][4];
#pragma unroll
            for (int mt = 0; mt < 4; ++mt)
                ldmx4(ah[mt], aB + (uint32_t)(mt * 16 * ROWB) + kb);
            uint32_t bh[2][4];
#pragma unroll
            for (int bt = 0; bt < 2; ++bt)
                ldmx4(bh[bt], bB + (uint32_t)(bt * 16 * ROWB) + kb);
#pragma unroll
            for (int mt = 0; mt < 4; ++mt) {
#pragma unroll
                for (int nt = 0; nt < 4; ++nt) {
                    const int bt = nt >> 1, o = nt & 1;
                    mma_f16(acc[mt][nt], ah[mt], bh[bt][o], bh[bt][o + 2]);
                }
            }
        }
    }

    // epilogue: bias + relu, float2 stores
    const int g = lid >> 2, t4 = lid & 3;
    float bb[4][2];
#pragma unroll
    for (int nt = 0; nt < 4; ++nt) {
        const int col = n0 + warp_n * 32 + nt * 8 + t4 * 2;
        bb[nt][0] = bias[col];
        bb[nt][1] = bias[col + 1];
    }
#pragma unroll
    for (int mt = 0; mt < 4; ++mt) {
        const int row = m0 + warp_m * 64 + mt * 16 + g;
#pragma unroll
        for (int nt = 0; nt < 4; ++nt) {
            const int col = n0 + warp_n * 32 + nt * 8 + t4 * 2;
            float2 v0, v1;
            v0.x = fmaxf(acc[mt][nt][0] + bb[nt][0], 0.f);
            v0.y = fmaxf(acc[mt][nt][1] + bb[nt][1], 0.f);
            v1.x = fmaxf(acc[mt][nt][2] + bb[nt][0], 0.f);
            v1.y = fmaxf(acc[mt][nt][3] + bb[nt][1], 0.f);
            *reinterpret_cast<float2*>(&C[(size_t)row * NDIM + col]) = v0;
            *reinterpret_cast<float2*>(&C[(size_t)(row + 8) * NDIM + col]) = v1;
        }
    }
}

// ---------------------------------------------------------------------------
// Launch
// ---------------------------------------------------------------------------
extern "C" void kernel_launch(void* const* d_in, const int* in_sizes, int n_in,
                              void* d_out, int out_size) {
    const float* x    = (const float*)d_in[0];
    const float* c1   = (const float*)d_in[1];
    const float* c2   = (const float*)d_in[2];
    const float* c3   = (const float*)d_in[3];
    const float* bias = (const float*)d_in[4];
    float* out = (float*)d_out;
    (void)in_sizes; (void)n_in; (void)out_size;

    cudaFuncSetAttribute(tt_gemm_f16,
                         cudaFuncAttributeMaxDynamicSharedMemorySize, DYN_BYTES);

    cvt_x_kernel<<<(BATCH * KDIM) / (4 * 256), 256>>>(x);
    w12_kernel<<<256, 256>>>(c1, c2);
    assemble_w_kernel<<<256, 256>>>(c3);

    dim3 grid(NDIM / BN, BATCH / BM);   // (32, 16) = 512 CTAs
    tt_gemm_f16<<<grid, 256, DYN_BYTES>>>(bias, out);
}

// round 7
// speedup vs baseline: 5.7111x; 1.0244x over previous
#include <cuda_runtime.h>
#include <cuda_fp16.h>
#include <cstdint>

// ============================================================================
// TensorDense via explicit-W:  out = relu(x @ W + bias)
//   W[(i,j,k),(a,b,c)] = sum_q (sum_p c1[i,a,p] c2[j,b,p,q]) c3[k,c,q]
// Single-product fp16 GEMM on legacy tensor cores (mma.sync, fp32 accum).
// BK=64 stages (half the barriers of BK=32), 3-stage cp.async ring, 2 CTA/SM.
// ============================================================================

#define MODE 16
#define KDIM 4096
#define NDIM 4096
#define BATCH 2048

__device__ float  g_W12[256 * 256 * 32];            // [ia][jb][q]  8MB
__device__ __half g_xh[(size_t)BATCH * KDIM];
__device__ __half g_wh[(size_t)NDIM * KDIM];        // W^T [n][k], fp16

// ---------------------------------------------------------------------------
// helpers (sm_80/sm_90-era only; ptxas targets bare sm_103)
// ---------------------------------------------------------------------------
__device__ __forceinline__ uint32_t smem_u32(const void* p) {
    uint32_t a;
    asm("{ .reg .u64 t; cvta.to.shared.u64 t, %1; cvt.u32.u64 %0, t; }"
        : "=r"(a) : "l"(p));
    return a;
}
__device__ __forceinline__ void cp_async16(uint32_t s, const void* g) {
    asm volatile("cp.async.cg.shared.global [%0], [%1], 16;" :: "r"(s), "l"(g));
}
#define CP_COMMIT() asm volatile("cp.async.commit_group;" ::: "memory")
#define CP_WAIT1()  asm volatile("cp.async.wait_group 1;"  ::: "memory")

__device__ __forceinline__ void ldmx4(uint32_t* r, uint32_t addr) {
    asm volatile("ldmatrix.sync.aligned.m8n8.x4.shared.b16 {%0,%1,%2,%3}, [%4];"
                 : "=r"(r[0]), "=r"(r[1]), "=r"(r[2]), "=r"(r[3]) : "r"(addr));
}
__device__ __forceinline__ void mma_f16(float* c, const uint32_t* a,
                                        uint32_t b0, uint32_t b1) {
    asm volatile(
        "mma.sync.aligned.m16n8k16.row.col.f32.f16.f16.f32 "
        "{%0,%1,%2,%3}, {%4,%5,%6,%7}, {%8,%9}, {%0,%1,%2,%3};"
        : "+f"(c[0]), "+f"(c[1]), "+f"(c[2]), "+f"(c[3])
        : "r"(a[0]), "r"(a[1]), "r"(a[2]), "r"(a[3]), "r"(b0), "r"(b1));
}

// ---------------------------------------------------------------------------
// Kernel 1: x -> fp16
// ---------------------------------------------------------------------------
__global__ void cvt_x_kernel(const float* __restrict__ x) {
    const size_t t = (size_t)blockIdx.x * 256 + threadIdx.x;
    float4 v = reinterpret_cast<const float4*>(x)[t];
    __half2 h01 = __floats2half2_rn(v.x, v.y);
    __half2 h23 = __floats2half2_rn(v.z, v.w);
    reinterpret_cast<__half2*>(g_xh)[t * 2 + 0] = h01;
    reinterpret_cast<__half2*>(g_xh)[t * 2 + 1] = h23;
}

// ---------------------------------------------------------------------------
// Kernel 2: W12[ia][jb][q] = sum_p c1[ia][p] * c2[jb][p][q]. CTA/jb, thr/ia.
// ---------------------------------------------------------------------------
__global__ void w12_kernel(const float* __restrict__ c1,
                           const float* __restrict__ c2) {
    __shared__ float sc2[1024];
    const int jb = blockIdx.x;
    const int tid = threadIdx.x;              // = ia

    reinterpret_cast<float4*>(sc2)[tid] =
        reinterpret_cast<const float4*>(c2 + (size_t)jb * 1024)[tid];

    float4 c1v[8];
    const float4* c1p = reinterpret_cast<const float4*>(c1 + tid * 32);
#pragma unroll
    for (int u = 0; u < 8; ++u) c1v[u] = c1p[u];
    __syncthreads();

    float4 acc[8];
#pragma unroll
    for (int u = 0; u < 8; ++u) acc[u] = make_float4(0.f, 0.f, 0.f, 0.f);

    const float4* sc2v = reinterpret_cast<const float4*>(sc2);
    const float* c1s = reinterpret_cast<const float*>(c1v);
#pragma unroll
    for (int p = 0; p < 32; ++p) {
        const float cp = c1s[p];
#pragma unroll
        for (int q4 = 0; q4 < 8; ++q4) {
            float4 w = sc2v[p * 8 + q4];
            acc[q4].x = fmaf(cp, w.x, acc[q4].x);
            acc[q4].y = fmaf(cp, w.y, acc[q4].y);
            acc[q4].z = fmaf(cp, w.z, acc[q4].z);
            acc[q4].w = fmaf(cp, w.w, acc[q4].w);
        }
    }
    float4* outp = reinterpret_cast<float4*>(g_W12 + ((size_t)tid * 256 + jb) * 32);
#pragma unroll
    for (int u = 0; u < 8; ++u) outp[u] = acc[u];
}

// ---------------------------------------------------------------------------
// Kernel 3: assemble W^T in fp16. CTA per (i,j), thread per (a,b).
// ---------------------------------------------------------------------------
__global__ void assemble_w_kernel(const float* __restrict__ c3) {
    __shared__ float sc3[8192];               // [kz][c][q] 32KB
    const int ij = blockIdx.x;
    const int tid = threadIdx.x;              // ab
    const int a = tid >> 4, b = tid & 15;
    const int i = ij >> 4, j = ij & 15;

    const float4* c3g = reinterpret_cast<const float4*>(c3);
    float4* sc3w = reinterpret_cast<float4*>(sc3);
#pragma unroll
    for (int u = 0; u < 8; ++u) sc3w[u * 256 + tid] = c3g[u * 256 + tid];

    float4 w12v[8];
    const float4* wp = reinterpret_cast<const float4*>(
        g_W12 + ((size_t)(i * 16 + a) * 256 + (j * 16 + b)) * 32);
#pragma unroll
    for (int u = 0; u < 8; ++u) w12v[u] = wp[u];
    __syncthreads();

    const float4* sc3v = reinterpret_cast<const float4*>(sc3);
#pragma unroll 1
    for (int c = 0; c < 16; ++c) {
        float acc[16];
#pragma unroll
        for (int kz = 0; kz < 16; ++kz) acc[kz] = 0.f;
#pragma unroll
        for (int q4 = 0; q4 < 8; ++q4) {
            const float4 w = w12v[q4];
#pragma unroll
            for (int kz = 0; kz < 16; ++kz) {
                float4 cv = sc3v[(kz * 16 + c) * 8 + q4];   // warp broadcast
                acc[kz] = fmaf(w.x, cv.x, acc[kz]);
                acc[kz] = fmaf(w.y, cv.y, acc[kz]);
                acc[kz] = fmaf(w.z, cv.z, acc[kz]);
                acc[kz] = fmaf(w.w, cv.w, acc[kz]);
            }
        }
        __half2 hv[8];
#pragma unroll
        for (int u = 0; u < 8; ++u)
            hv[u] = __floats2half2_rn(acc[u * 2], acc[u * 2 + 1]);
        __half* dst = g_wh + (size_t)(tid * 16 + c) * KDIM + ij * 16;
        reinterpret_cast<uint4*>(dst)[0] = reinterpret_cast<uint4*>(hv)[0];
        reinterpret_cast<uint4*>(dst)[1] = reinterpret_cast<uint4*>(hv)[1];
    }
}

// ---------------------------------------------------------------------------
// Kernel 4: single-product fp16 GEMM.
// CTA tile 128x128, BK=64 per stage, 8 warps (2m x 4n), warp tile 64x32.
// 3-stage cp.async ring, ONE __syncthreads per 64-k stage, 2 CTAs/SM.
// SMEM rows: 128B data + 16B pad = 144B (banks 4r%32 distinct -> no conflicts).
// ---------------------------------------------------------------------------
#define BM 128
#define BN 128
#define ROWB 144
#define ARR_BYTES (128 * ROWB)          // 18432
#define STAGE_BYTES (2 * ARR_BYTES)     // xh | wh = 36864
#define STAGES 3
#define DYN_BYTES (STAGES * STAGE_BYTES)  // 110592

__global__ __launch_bounds__(256, 2)
void tt_gemm_f16(const float* __restrict__ bias, float* __restrict__ C) {
    extern __shared__ __align__(16) char dyn[];
    const uint32_t dynU = smem_u32(dyn);

    const int tid = threadIdx.x;
    const int wid = tid >> 5;
    const int lid = tid & 31;
    const int warp_m = wid & 1;      // 64 rows each
    const int warp_n = wid >> 1;     // 32 cols each
    const int m0 = blockIdx.y * BM;
    const int n0 = blockIdx.x * BN;

    const char* xh = (const char*)g_xh;
    const char* wh = (const char*)g_wh;

    // loader mapping: 128 rows x 128B (8 chunks of 16B); 4 chunks/thread/array
    uint32_t sOff[4];
    size_t gAOff[4], gBOff[4];
#pragma unroll
    for (int u = 0; u < 4; ++u) {
        const int ci = u * 256 + tid;        // 0..1023
        const int r = ci >> 3, ch = (ci & 7) * 16;
        sOff[u] = (uint32_t)(r * ROWB + ch);
        gAOff[u] = (size_t)(m0 + r) * (KDIM * 2) + ch;
        gBOff[u] = (size_t)(n0 + r) * (KDIM * 2) + ch;
    }

    float acc[4][4][4];
#pragma unroll
    for (int a = 0; a < 4; ++a)
#pragma unroll
        for (int b = 0; b < 4; ++b)
#pragma unroll
            for (int c = 0; c < 4; ++c) acc[a][b][c] = 0.f;

    const uint32_t lmRow = (uint32_t)(lid & 15);
    const uint32_t lmCol = (uint32_t)((lid >> 4) * 16);
    const uint32_t aLM = (uint32_t)((warp_m * 64 + lmRow) * ROWB) + lmCol;
    const uint32_t bLM = (uint32_t)((warp_n * 32 + lmRow) * ROWB) + lmCol;

    auto load_stage = [&](int kt) {
        const uint32_t sb = dynU + (uint32_t)((kt % STAGES)) * STAGE_BYTES;
        const size_t ko = (size_t)kt * 128;   // 64 halves = 128B along k
#pragma unroll
        for (int u = 0; u < 4; ++u) {
            cp_async16(sb + sOff[u],             xh + gAOff[u] + ko);
            cp_async16(sb + ARR_BYTES + sOff[u], wh + gBOff[u] + ko);
        }
    };

    // preload stages 0,1
    load_stage(0); CP_COMMIT();
    load_stage(1); CP_COMMIT();

    const int numK = KDIM / 64;      // 64 stages
    for (int kt = 0; kt < numK; ++kt) {
        CP_WAIT1();                  // stage kt arrived (1 group may be pending)
        __syncthreads();             // publish stage kt; stage kt-1 fully consumed

        if (kt + 2 < numK) load_stage(kt + 2);
        CP_COMMIT();                 // uniform group accounting

        const uint32_t sb = dynU + (uint32_t)((kt % STAGES)) * STAGE_BYTES;
        const uint32_t aB = sb + aLM;
        const uint32_t bB = sb + ARR_BYTES + bLM;

#pragma unroll
        for (int ks = 0; ks < 4; ++ks) {             // four k16 steps
            const uint32_t kb = (uint32_t)(ks * 32); // 16 halves = 32B
            uint32_t ah[4][4];
#pragma unroll
            for (int mt = 0; mt < 4; ++mt)
                ldmx4(ah[mt], aB + (uint32_t)(mt * 16 * ROWB) + kb);
            uint32_t bh[2][4];
#pragma unroll
            for (int bt = 0; bt < 2; ++bt)
                ldmx4(bh[bt], bB + (uint32_t)(bt * 16 * ROWB) + kb);
#pragma unroll
            for (int mt = 0; mt < 4; ++mt) {
#pragma unroll
                for (int nt = 0; nt < 4; ++nt) {
                    const int bt = nt >> 1, o = nt & 1;
                    mma_f16(acc[mt][nt], ah[mt], bh[bt][o], bh[bt][o + 2]);
                }
            }
        }
    }

    // epilogue: bias + relu, float2 stores
    const int g = lid >> 2, t4 = lid & 3;
    float bb[4][2];
#pragma unroll
    for (int nt = 0; nt < 4; ++nt) {
        const int col = n0 + warp_n * 32 + nt * 8 + t4 * 2;
        bb[nt][0] = bias[col];
        bb[nt][1] = bias[col + 1];
    }
#pragma unroll
    for (int mt = 0; mt < 4; ++mt) {
        const int row = m0 + warp_m * 64 + mt * 16 + g;
#pragma unroll
        for (int nt = 0; nt < 4; ++nt) {
            const int col = n0 + warp_n * 32 + nt * 8 + t4 * 2;
            float2 v0, v1;
            v0.x = fmaxf(acc[mt][nt][0] + bb[nt][0], 0.f);
            v0.y = fmaxf(acc[mt][nt][1] + bb[nt][1], 0.f);
            v1.x = fmaxf(acc[mt][nt][2] + bb[nt][0], 0.f);
            v1.y = fmaxf(acc[mt][nt][3] + bb[nt][1], 0.f);
            *reinterpret_cast<float2*>(&C[(size_t)row * NDIM + col]) = v0;
            *reinterpret_cast<float2*>(&C[(size_t)(row + 8) * NDIM + col]) = v1;
        }
    }
}

// ---------------------------------------------------------------------------
// Launch
// ---------------------------------------------------------------------------
extern "C" void kernel_launch(void* const* d_in, const int* in_sizes, int n_in,
                              void* d_out, int out_size) {
    const float* x    = (const float*)d_in[0];
    const float* c1   = (const float*)d_in[1];
    const float* c2   = (const float*)d_in[2];
    const float* c3   = (const float*)d_in[3];
    const float* bias = (const float*)d_in[4];
    float* out = (float*)d_out;
    (void)in_sizes; (void)n_in; (void)out_size;

    cudaFuncSetAttribute(tt_gemm_f16,
                         cudaFuncAttributeMaxDynamicSharedMemorySize, DYN_BYTES);

    cvt_x_kernel<<<(BATCH * KDIM) / (4 * 256), 256>>>(x);
    w12_kernel<<<256, 256>>>(c1, c2);
    assemble_w_kernel<<<256, 256>>>(c3);

    dim3 grid(NDIM / BN, BATCH / BM);   // (32, 16) = 512 CTAs
    tt_gemm_f16<<<grid, 256, DYN_BYTES>>>(bias, out);
}